// round 4
// baseline (speedup 1.0000x reference)
#include <cuda_runtime.h>
#include <cstdint>

// ---------------------------------------------------------------------------
// Problem constants
// ---------------------------------------------------------------------------
#define NMI 100000
#define NDI 50000
#define HMAX 256

// ---------------------------------------------------------------------------
// Scratch: __device__ globals
// ---------------------------------------------------------------------------
__device__ float g_hmi_a[(size_t)NMI * HMAX];
__device__ float g_hmi_b[(size_t)NMI * HMAX];
__device__ float g_hdi_a[(size_t)NDI * HMAX];
__device__ float g_hdi_b[(size_t)NDI * HMAX];
__device__ float g_agg_mi[(size_t)NMI * HMAX];
__device__ float g_agg_di[(size_t)NDI * HMAX];
__device__ float g_deg_mi[NMI];
__device__ float g_deg_di[NDI];

static inline int cdiv(int a, int b) { return (a + b - 1) / b; }

// ---------------------------------------------------------------------------
// Degree count + inversion
// ---------------------------------------------------------------------------
__global__ void deg_kernel(const int* __restrict__ src, const int* __restrict__ dst,
                           int E, float* __restrict__ deg_mi, float* __restrict__ deg_di)
{
    int i = blockIdx.x * blockDim.x + threadIdx.x;
    if (i < E) {
        atomicAdd(&deg_mi[src[i]], 1.0f);
        atomicAdd(&deg_di[dst[i]], 1.0f);
    }
}

__global__ void inv_kernel(float* __restrict__ deg, int n)
{
    int i = blockIdx.x * blockDim.x + threadIdx.x;
    if (i < n) deg[i] = 1.0f / fmaxf(deg[i], 1.0f);
}

// ---------------------------------------------------------------------------
// Vectorized global reduction
// ---------------------------------------------------------------------------
__device__ __forceinline__ void red_add_v4(float* p, float4 v)
{
    asm volatile("red.global.add.v4.f32 [%0], {%1, %2, %3, %4};"
                 :: "l"(p), "f"(v.x), "f"(v.y), "f"(v.z), "f"(v.w)
                 : "memory");
}

// ---------------------------------------------------------------------------
// Fused bidirectional scatter: one warp per edge.
// ---------------------------------------------------------------------------
__global__ void scatter_kernel(const float* __restrict__ hmi, const float* __restrict__ hdi,
                               const int* __restrict__ src, const int* __restrict__ dst,
                               int E, int C,
                               float* __restrict__ agg_di, float* __restrict__ agg_mi)
{
    int gw = (blockIdx.x * blockDim.x + threadIdx.x) >> 5;
    int lane = threadIdx.x & 31;
    if (gw >= E) return;
    int s = src[gw];
    int d = dst[gw];
    const float4* rs = (const float4*)(hmi + (size_t)s * C);
    const float4* rd = (const float4*)(hdi + (size_t)d * C);
    float*        ad = agg_di + (size_t)d * C;
    float*        am = agg_mi + (size_t)s * C;
    int n4 = C >> 2;
    for (int j = lane; j < n4; j += 32) {
        float4 a = rs[j];
        float4 b = rd[j];
        red_add_v4(ad + j * 4, a);
        red_add_v4(am + j * 4, b);
    }
}

// ---------------------------------------------------------------------------
// 3xTF32 mma.sync GEMM (fp32-level accuracy via hi/lo split)
//   D[n,c] = sum_k s(n)*A1[n,k]*W1[c,k] (+ sum_k A2[n,k]*W2[c,k])
//            + bias[c] (+ addend[n,c]) ; optional relu
// CTA: 256 threads (8 warps, 4x2), tile 128x128, warp tile 32x64, BK=16.
// ---------------------------------------------------------------------------
#define BM 128
#define BN 128
#define BK 16
#define KPAD 4           // smem row stride = 20 uints

__device__ __forceinline__ unsigned f2tf32(float f)
{
    unsigned u;
    asm("cvt.rna.tf32.f32 %0, %1;" : "=r"(u) : "f"(f));
    return u;
}

__device__ __forceinline__ void mma_tf32(float* d, const unsigned* a, unsigned b0, unsigned b1)
{
    asm volatile(
        "mma.sync.aligned.m16n8k8.row.col.f32.tf32.tf32.f32 "
        "{%0,%1,%2,%3}, {%4,%5,%6,%7}, {%8,%9}, {%0,%1,%2,%3};"
        : "+f"(d[0]), "+f"(d[1]), "+f"(d[2]), "+f"(d[3])
        : "r"(a[0]), "r"(a[1]), "r"(a[2]), "r"(a[3]), "r"(b0), "r"(b1));
}

__global__ __launch_bounds__(256, 2)
void gemm_3xtf32(const float* __restrict__ A1, const float* __restrict__ invdeg,
                 const float* __restrict__ W1,
                 const float* __restrict__ A2, const float* __restrict__ W2,
                 const float* __restrict__ bias, const float* __restrict__ addend,
                 float* __restrict__ D, int N, int K, int Co, int relu)
{
    __shared__ unsigned As_h[BM][BK + KPAD];
    __shared__ unsigned As_l[BM][BK + KPAD];
    __shared__ unsigned Bs_h[BN][BK + KPAD];
    __shared__ unsigned Bs_l[BN][BK + KPAD];

    const int tid  = threadIdx.x;
    const int lane = tid & 31;
    const int wid  = tid >> 5;
    const int wm   = (wid & 3) * 32;   // 4 warps along M
    const int wn   = (wid >> 2) * 64;  // 2 warps along N
    const int gid  = lane >> 2;        // 0..7
    const int tig  = lane & 3;         // 0..3

    const int row0 = blockIdx.x * BM;
    const int col0 = blockIdx.y * BN;

    const int lrow = tid >> 1;         // 0..127
    const int lc4  = tid & 1;          // 2 float4 col-groups per thread

    float acc[2][8][4];
#pragma unroll
    for (int i = 0; i < 2; i++)
#pragma unroll
        for (int j = 0; j < 8; j++)
#pragma unroll
            for (int q = 0; q < 4; q++) acc[i][j][q] = 0.0f;

    const int KT = (A2 != nullptr) ? 2 * K : K;

    const int a_row = row0 + lrow;
    const int b_col = col0 + lrow;
    const bool a_ok = a_row < N;
    const bool b_ok = b_col < Co;
    const float sc1 = (invdeg && a_ok) ? invdeg[a_row] : 1.0f;

    float4 pa[2], pb[2];

    auto load_tile = [&](int kt) {
        const bool first = kt < K;                // BK=16 tile never straddles
        const int  kk0   = first ? kt : (kt - K);
        const float* A   = first ? A1 : A2;
        const float* W   = first ? W1 : W2;
        const float  scl = first ? sc1 : 1.0f;
#pragma unroll
        for (int p = 0; p < 2; p++) {
            const int kk = kk0 + lc4 * 4 + p * 8;
            float4 v = make_float4(0.f, 0.f, 0.f, 0.f);
            if (a_ok) {
                v = *(const float4*)(A + (size_t)a_row * K + kk);
                v.x *= scl; v.y *= scl; v.z *= scl; v.w *= scl;
            }
            pa[p] = v;
            float4 w = make_float4(0.f, 0.f, 0.f, 0.f);
            if (b_ok) w = *(const float4*)(W + (size_t)b_col * K + kk);
            pb[p] = w;
        }
    };

    auto store_tile = [&]() {
#pragma unroll
        for (int p = 0; p < 2; p++) {
            const int kc = lc4 * 4 + p * 8;
            float4 v = pa[p];
            unsigned h0 = f2tf32(v.x), h1 = f2tf32(v.y), h2 = f2tf32(v.z), h3 = f2tf32(v.w);
            unsigned l0 = f2tf32(v.x - __uint_as_float(h0));
            unsigned l1 = f2tf32(v.y - __uint_as_float(h1));
            unsigned l2 = f2tf32(v.z - __uint_as_float(h2));
            unsigned l3 = f2tf32(v.w - __uint_as_float(h3));
            *(uint4*)&As_h[lrow][kc] = make_uint4(h0, h1, h2, h3);
            *(uint4*)&As_l[lrow][kc] = make_uint4(l0, l1, l2, l3);
            float4 w = pb[p];
            h0 = f2tf32(w.x); h1 = f2tf32(w.y); h2 = f2tf32(w.z); h3 = f2tf32(w.w);
            l0 = f2tf32(w.x - __uint_as_float(h0));
            l1 = f2tf32(w.y - __uint_as_float(h1));
            l2 = f2tf32(w.z - __uint_as_float(h2));
            l3 = f2tf32(w.w - __uint_as_float(h3));
            *(uint4*)&Bs_h[lrow][kc] = make_uint4(h0, h1, h2, h3);
            *(uint4*)&Bs_l[lrow][kc] = make_uint4(l0, l1, l2, l3);
        }
    };

    load_tile(0);

    for (int kt = 0; kt < KT; kt += BK) {
        store_tile();
        __syncthreads();
        if (kt + BK < KT) load_tile(kt + BK);

#pragma unroll
        for (int k8 = 0; k8 < 2; k8++) {
            const int kb = k8 * 8;
            unsigned ah[2][4], al[2][4];
#pragma unroll
            for (int mi = 0; mi < 2; mi++) {
                int r = wm + mi * 16 + gid;
                ah[mi][0] = As_h[r][kb + tig];
                ah[mi][1] = As_h[r + 8][kb + tig];
                ah[mi][2] = As_h[r][kb + tig + 4];
                ah[mi][3] = As_h[r + 8][kb + tig + 4];
                al[mi][0] = As_l[r][kb + tig];
                al[mi][1] = As_l[r + 8][kb + tig];
                al[mi][2] = As_l[r][kb + tig + 4];
                al[mi][3] = As_l[r + 8][kb + tig + 4];
            }
#pragma unroll
            for (int ni = 0; ni < 8; ni++) {
                int c = wn + ni * 8 + gid;
                unsigned bh0 = Bs_h[c][kb + tig];
                unsigned bh1 = Bs_h[c][kb + tig + 4];
                unsigned bl0 = Bs_l[c][kb + tig];
                unsigned bl1 = Bs_l[c][kb + tig + 4];
#pragma unroll
                for (int mi = 0; mi < 2; mi++) {
                    mma_tf32(acc[mi][ni], al[mi], bh0, bh1);   // lo*hi
                    mma_tf32(acc[mi][ni], ah[mi], bl0, bl1);   // hi*lo
                    mma_tf32(acc[mi][ni], ah[mi], bh0, bh1);   // hi*hi
                }
            }
        }
        __syncthreads();
    }

    // ---- epilogue ----
#pragma unroll
    for (int mi = 0; mi < 2; mi++) {
#pragma unroll
        for (int ni = 0; ni < 8; ni++) {
            int col = col0 + wn + ni * 8 + 2 * tig;
            if (col >= Co) continue;
            float b0 = bias ? bias[col]     : 0.0f;
            float b1 = bias ? bias[col + 1] : 0.0f;
#pragma unroll
            for (int half = 0; half < 2; half++) {
                int row = row0 + wm + mi * 16 + gid + half * 8;
                if (row >= N) continue;
                float v0 = acc[mi][ni][half * 2 + 0] + b0;
                float v1 = acc[mi][ni][half * 2 + 1] + b1;
                if (addend) {
                    float2 ad = *(const float2*)(addend + (size_t)row * Co + col);
                    v0 += ad.x; v1 += ad.y;
                }
                if (relu) { v0 = fmaxf(v0, 0.0f); v1 = fmaxf(v1, 0.0f); }
                *(float2*)(D + (size_t)row * Co + col) = make_float2(v0, v1);
            }
        }
    }
}

// ---------------------------------------------------------------------------
// Classifier dot product
// ---------------------------------------------------------------------------
__global__ void dot_kernel(const float* __restrict__ hmi, const float* __restrict__ hdi,
                           const int* __restrict__ lsrc, const int* __restrict__ ldst,
                           int L, float* __restrict__ out)
{
    int idx = blockIdx.x * blockDim.x + threadIdx.x;
    int lab = idx >> 4;
    int ln  = idx & 15;
    if (lab >= L) return;
    int s = lsrc[lab];
    int d = ldst[lab];
    float4 a = *(const float4*)(hmi + (size_t)s * 64 + ln * 4);
    float4 b = *(const float4*)(hdi + (size_t)d * 64 + ln * 4);
    float v = a.x * b.x + a.y * b.y + a.z * b.z + a.w * b.w;
    v += __shfl_down_sync(0xFFFFFFFFu, v, 8, 16);
    v += __shfl_down_sync(0xFFFFFFFFu, v, 4, 16);
    v += __shfl_down_sync(0xFFFFFFFFu, v, 2, 16);
    v += __shfl_down_sync(0xFFFFFFFFu, v, 1, 16);
    if (ln == 0) out[lab] = v;
}

// ---------------------------------------------------------------------------
// Launch
// ---------------------------------------------------------------------------
extern "C" void kernel_launch(void* const* d_in, const int* in_sizes, int n_in,
                              void* d_out, int out_size)
{
    const float* x_mi   = (const float*)d_in[0];
    const float* x_di   = (const float*)d_in[1];
    const float* W_mi   = (const float*)d_in[2];
    const float* b_mi   = (const float*)d_in[3];
    const float* W_di   = (const float*)d_in[4];
    const float* b_di   = (const float*)d_in[5];
    const float* emb_mi = (const float*)d_in[6];
    const float* emb_di = (const float*)d_in[7];

    const float *Wl[3][2], *bl[3][2], *Wr[3][2];  // [layer][0=md,1=dm]
    int idx = 8;
    for (int l = 0; l < 3; l++)
        for (int r = 0; r < 2; r++) {
            Wl[l][r] = (const float*)d_in[idx++];
            bl[l][r] = (const float*)d_in[idx++];
            Wr[l][r] = (const float*)d_in[idx++];
        }
    const int* edge_src  = (const int*)d_in[26];
    const int* edge_dst  = (const int*)d_in[27];
    const int* label_src = (const int*)d_in[28];
    const int* label_dst = (const int*)d_in[29];
    const int E = in_sizes[26];
    const int L = in_sizes[28];
    float* out = (float*)d_out;

    float *hmi[2], *hdi[2], *agg_mi, *agg_di, *deg_mi, *deg_di;
    cudaGetSymbolAddress((void**)&hmi[0], g_hmi_a);
    cudaGetSymbolAddress((void**)&hmi[1], g_hmi_b);
    cudaGetSymbolAddress((void**)&hdi[0], g_hdi_a);
    cudaGetSymbolAddress((void**)&hdi[1], g_hdi_b);
    cudaGetSymbolAddress((void**)&agg_mi, g_agg_mi);
    cudaGetSymbolAddress((void**)&agg_di, g_agg_di);
    cudaGetSymbolAddress((void**)&deg_mi, g_deg_mi);
    cudaGetSymbolAddress((void**)&deg_di, g_deg_di);

    cudaStream_t s = 0;

    cudaMemsetAsync(deg_mi, 0, (size_t)NMI * sizeof(float), s);
    cudaMemsetAsync(deg_di, 0, (size_t)NDI * sizeof(float), s);
    deg_kernel<<<cdiv(E, 256), 256, 0, s>>>(edge_src, edge_dst, E, deg_mi, deg_di);
    inv_kernel<<<cdiv(NMI, 256), 256, 0, s>>>(deg_mi, NMI);
    inv_kernel<<<cdiv(NDI, 256), 256, 0, s>>>(deg_di, NDI);

    // input projections: h = x @ W^T + b + emb
    gemm_3xtf32<<<dim3(cdiv(NDI, BM), 1), 256, 0, s>>>(
        x_di, nullptr, W_di, nullptr, nullptr, b_di, emb_di, hdi[0],
        NDI, 128, 128, 0);
    gemm_3xtf32<<<dim3(cdiv(NMI, BM), 1), 256, 0, s>>>(
        x_mi, nullptr, W_mi, nullptr, nullptr, b_mi, emb_mi, hmi[0],
        NMI, 256, 128, 0);

    const int cin[3]  = {128, 256, 128};
    const int cout[3] = {256, 128, 64};
    int cur = 0;
    for (int l = 0; l < 3; l++) {
        int K  = cin[l];
        int Co = cout[l];
        int relu = (l < 2) ? 1 : 0;

        cudaMemsetAsync(agg_mi, 0, (size_t)NMI * K * sizeof(float), s);
        cudaMemsetAsync(agg_di, 0, (size_t)NDI * K * sizeof(float), s);
        scatter_kernel<<<cdiv(E * 32, 256), 256, 0, s>>>(
            hmi[cur], hdi[cur], edge_src, edge_dst, E, K, agg_di, agg_mi);

        gemm_3xtf32<<<dim3(cdiv(NDI, BM), cdiv(Co, BN)), 256, 0, s>>>(
            agg_di, deg_di, Wl[l][0], hdi[cur], Wr[l][0], bl[l][0], nullptr,
            hdi[cur ^ 1], NDI, K, Co, relu);
        gemm_3xtf32<<<dim3(cdiv(NMI, BM), cdiv(Co, BN)), 256, 0, s>>>(
            agg_mi, deg_mi, Wl[l][1], hmi[cur], Wr[l][1], bl[l][1], nullptr,
            hmi[cur ^ 1], NMI, K, Co, relu);

        cur ^= 1;
    }

    dot_kernel<<<cdiv(L * 16, 256), 256, 0, s>>>(
        hmi[cur], hdi[cur], label_src, label_dst, L, out);
}

// round 6
// speedup vs baseline: 1.3340x; 1.3340x over previous
#include <cuda_runtime.h>
#include <cstdint>

// ---------------------------------------------------------------------------
// Problem constants
// ---------------------------------------------------------------------------
#define NMI 100000
#define NDI 50000
#define HMAX 256

// ---------------------------------------------------------------------------
// Scratch: __device__ globals
// ---------------------------------------------------------------------------
__device__ float g_hmi_a[(size_t)NMI * HMAX];
__device__ float g_hmi_b[(size_t)NMI * HMAX];
__device__ float g_hdi_a[(size_t)NDI * HMAX];
__device__ float g_hdi_b[(size_t)NDI * HMAX];
__device__ float g_agg_mi[(size_t)NMI * HMAX];
__device__ float g_agg_di[(size_t)NDI * HMAX];
__device__ float g_deg_mi[NMI];
__device__ float g_deg_di[NDI];

static inline int cdiv(int a, int b) { return (a + b - 1) / b; }

// ---------------------------------------------------------------------------
// Degree count + inversion
// ---------------------------------------------------------------------------
__global__ void deg_kernel(const int* __restrict__ src, const int* __restrict__ dst,
                           int E, float* __restrict__ deg_mi, float* __restrict__ deg_di)
{
    int i = blockIdx.x * blockDim.x + threadIdx.x;
    if (i < E) {
        atomicAdd(&deg_mi[src[i]], 1.0f);
        atomicAdd(&deg_di[dst[i]], 1.0f);
    }
}

__global__ void inv_kernel(float* __restrict__ deg, int n)
{
    int i = blockIdx.x * blockDim.x + threadIdx.x;
    if (i < n) deg[i] = 1.0f / fmaxf(deg[i], 1.0f);
}

// ---------------------------------------------------------------------------
// Vectorized global reduction
// ---------------------------------------------------------------------------
__device__ __forceinline__ void red_add_v4(float* p, float4 v)
{
    asm volatile("red.global.add.v4.f32 [%0], {%1, %2, %3, %4};"
                 :: "l"(p), "f"(v.x), "f"(v.y), "f"(v.z), "f"(v.w)
                 : "memory");
}

// ---------------------------------------------------------------------------
// Fused bidirectional scatter: one warp per edge.
// ---------------------------------------------------------------------------
__global__ void scatter_kernel(const float* __restrict__ hmi, const float* __restrict__ hdi,
                               const int* __restrict__ src, const int* __restrict__ dst,
                               int E, int C,
                               float* __restrict__ agg_di, float* __restrict__ agg_mi)
{
    int gw = (blockIdx.x * blockDim.x + threadIdx.x) >> 5;
    int lane = threadIdx.x & 31;
    if (gw >= E) return;
    int s = src[gw];
    int d = dst[gw];
    const float4* rs = (const float4*)(hmi + (size_t)s * C);
    const float4* rd = (const float4*)(hdi + (size_t)d * C);
    float*        ad = agg_di + (size_t)d * C;
    float*        am = agg_mi + (size_t)s * C;
    int n4 = C >> 2;
    for (int j = lane; j < n4; j += 32) {
        float4 a = rs[j];
        float4 b = rd[j];
        red_add_v4(ad + j * 4, a);
        red_add_v4(am + j * 4, b);
    }
}

// ---------------------------------------------------------------------------
// Split-precision bf16 GEMM (bf16x3: hi/lo split, 3 product terms)
//   D[n,c] = sum_k s(n)*A1[n,k]*W1[c,k] (+ sum_k A2[n,k]*W2[c,k])
//            + bias[c] (+ addend[n,c]) ; optional relu
// CTA: 256 threads (8 warps, 4 along M x 2 along N), tile 128x128,
// warp tile 32x64, BK=16 (one m16n8k16 step per iter).
// SMEM uint arrays pack 2 bf16 along K; row stride 12 uints (conflict-free).
// ---------------------------------------------------------------------------
#define BM 128
#define BN 128
#define BK 16
#define SR 12          // smem row stride in uints (8 data + 4 pad)

__device__ __forceinline__ unsigned pack_bf16x2(float even, float odd)
{
    unsigned u;
    // d = { a(high)=odd, b(low)=even }
    asm("cvt.rn.bf16x2.f32 %0, %1, %2;" : "=r"(u) : "f"(odd), "f"(even));
    return u;
}

// split 4 floats (k, k+1, k+2, k+3) into hi/lo packed pairs
__device__ __forceinline__ void split4(float4 v, unsigned& h0, unsigned& h1,
                                       unsigned& l0, unsigned& l1)
{
    h0 = pack_bf16x2(v.x, v.y);
    h1 = pack_bf16x2(v.z, v.w);
    float ex = v.x - __uint_as_float(h0 << 16);
    float ey = v.y - __uint_as_float(h0 & 0xFFFF0000u);
    float ez = v.z - __uint_as_float(h1 << 16);
    float ew = v.w - __uint_as_float(h1 & 0xFFFF0000u);
    l0 = pack_bf16x2(ex, ey);
    l1 = pack_bf16x2(ez, ew);
}

__device__ __forceinline__ void mma_bf16(float* d, const unsigned* a, unsigned b0, unsigned b1)
{
    asm volatile(
        "mma.sync.aligned.m16n8k16.row.col.f32.bf16.bf16.f32 "
        "{%0,%1,%2,%3}, {%4,%5,%6,%7}, {%8,%9}, {%0,%1,%2,%3};"
        : "+f"(d[0]), "+f"(d[1]), "+f"(d[2]), "+f"(d[3])
        : "r"(a[0]), "r"(a[1]), "r"(a[2]), "r"(a[3]), "r"(b0), "r"(b1));
}

__global__ __launch_bounds__(256, 2)
void gemm_bf16x3(const float* __restrict__ A1, const float* __restrict__ invdeg,
                 const float* __restrict__ W1,
                 const float* __restrict__ A2, const float* __restrict__ W2,
                 const float* __restrict__ bias, const float* __restrict__ addend,
                 float* __restrict__ D, int N, int K, int Co, int relu)
{
    __shared__ unsigned As_h[BM][SR];
    __shared__ unsigned As_l[BM][SR];
    __shared__ unsigned Bs_h[BN][SR];
    __shared__ unsigned Bs_l[BN][SR];

    const int tid  = threadIdx.x;
    const int lane = tid & 31;
    const int wid  = tid >> 5;
    const int wm   = (wid & 3) * 32;   // 4 warps along M
    const int wn   = (wid >> 2) * 64;  // 2 warps along N
    const int gid  = lane >> 2;        // 0..7
    const int tig  = lane & 3;         // 0..3

    const int row0 = blockIdx.x * BM;
    const int col0 = blockIdx.y * BN;

    const int lrow = tid >> 1;         // 0..127
    const int lh   = tid & 1;          // which k8-half this thread loads

    float acc[2][8][4];
#pragma unroll
    for (int i = 0; i < 2; i++)
#pragma unroll
        for (int j = 0; j < 8; j++)
#pragma unroll
            for (int q = 0; q < 4; q++) acc[i][j][q] = 0.0f;

    const int KT = (A2 != nullptr) ? 2 * K : K;

    const int a_row = row0 + lrow;
    const int b_col = col0 + lrow;
    const bool a_ok = a_row < N;
    const bool b_ok = b_col < Co;
    const float sc1 = (invdeg && a_ok) ? invdeg[a_row] : 1.0f;

    float4 pa[2], pb[2];

    auto load_tile = [&](int kt) {
        const bool first = kt < K;                 // BK=16 tile never straddles
        const int  kk0   = first ? kt : (kt - K);
        const float* A   = first ? A1 : A2;
        const float* W   = first ? W1 : W2;
        const float  scl = first ? sc1 : 1.0f;
#pragma unroll
        for (int p = 0; p < 2; p++) {
            const int kk = kk0 + lh * 8 + p * 4;   // contiguous k8 per thread
            float4 v = make_float4(0.f, 0.f, 0.f, 0.f);
            if (a_ok) {
                v = *(const float4*)(A + (size_t)a_row * K + kk);
                v.x *= scl; v.y *= scl; v.z *= scl; v.w *= scl;
            }
            pa[p] = v;
            float4 w = make_float4(0.f, 0.f, 0.f, 0.f);
            if (b_ok) w = *(const float4*)(W + (size_t)b_col * K + kk);
            pb[p] = w;
        }
    };

    auto store_tile = [&]() {
        unsigned h0, h1, h2, h3, l0, l1, l2, l3;
        split4(pa[0], h0, h1, l0, l1);
        split4(pa[1], h2, h3, l2, l3);
        *(uint4*)&As_h[lrow][lh * 4] = make_uint4(h0, h1, h2, h3);
        *(uint4*)&As_l[lrow][lh * 4] = make_uint4(l0, l1, l2, l3);
        split4(pb[0], h0, h1, l0, l1);
        split4(pb[1], h2, h3, l2, l3);
        *(uint4*)&Bs_h[lrow][lh * 4] = make_uint4(h0, h1, h2, h3);
        *(uint4*)&Bs_l[lrow][lh * 4] = make_uint4(l0, l1, l2, l3);
    };

    load_tile(0);

    for (int kt = 0; kt < KT; kt += BK) {
        store_tile();
        __syncthreads();
        if (kt + BK < KT) load_tile(kt + BK);

        unsigned ah[2][4], al[2][4];
#pragma unroll
        for (int mi = 0; mi < 2; mi++) {
            int r = wm + mi * 16 + gid;
            ah[mi][0] = As_h[r][tig];
            ah[mi][1] = As_h[r + 8][tig];
            ah[mi][2] = As_h[r][tig + 4];
            ah[mi][3] = As_h[r + 8][tig + 4];
            al[mi][0] = As_l[r][tig];
            al[mi][1] = As_l[r + 8][tig];
            al[mi][2] = As_l[r][tig + 4];
            al[mi][3] = As_l[r + 8][tig + 4];
        }
#pragma unroll
        for (int ni = 0; ni < 8; ni++) {
            int c = wn + ni * 8 + gid;
            unsigned bh0 = Bs_h[c][tig];
            unsigned bh1 = Bs_h[c][tig + 4];
            unsigned bl0 = Bs_l[c][tig];
            unsigned bl1 = Bs_l[c][tig + 4];
#pragma unroll
            for (int mi = 0; mi < 2; mi++) {
                mma_bf16(acc[mi][ni], al[mi], bh0, bh1);   // lo*hi
                mma_bf16(acc[mi][ni], ah[mi], bl0, bl1);   // hi*lo
                mma_bf16(acc[mi][ni], ah[mi], bh0, bh1);   // hi*hi
            }
        }
        __syncthreads();
    }

    // ---- epilogue ----
#pragma unroll
    for (int mi = 0; mi < 2; mi++) {
#pragma unroll
        for (int ni = 0; ni < 8; ni++) {
            int col = col0 + wn + ni * 8 + 2 * tig;
            if (col >= Co) continue;
            float b0 = bias ? bias[col]     : 0.0f;
            float b1 = bias ? bias[col + 1] : 0.0f;
#pragma unroll
            for (int half = 0; half < 2; half++) {
                int row = row0 + wm + mi * 16 + gid + half * 8;
                if (row >= N) continue;
                float v0 = acc[mi][ni][half * 2 + 0] + b0;
                float v1 = acc[mi][ni][half * 2 + 1] + b1;
                if (addend) {
                    float2 ad = *(const float2*)(addend + (size_t)row * Co + col);
                    v0 += ad.x; v1 += ad.y;
                }
                if (relu) { v0 = fmaxf(v0, 0.0f); v1 = fmaxf(v1, 0.0f); }
                *(float2*)(D + (size_t)row * Co + col) = make_float2(v0, v1);
            }
        }
    }
}

// ---------------------------------------------------------------------------
// Classifier dot product
// ---------------------------------------------------------------------------
__global__ void dot_kernel(const float* __restrict__ hmi, const float* __restrict__ hdi,
                           const int* __restrict__ lsrc, const int* __restrict__ ldst,
                           int L, float* __restrict__ out)
{
    int idx = blockIdx.x * blockDim.x + threadIdx.x;
    int lab = idx >> 4;
    int ln  = idx & 15;
    if (lab >= L) return;
    int s = lsrc[lab];
    int d = ldst[lab];
    float4 a = *(const float4*)(hmi + (size_t)s * 64 + ln * 4);
    float4 b = *(const float4*)(hdi + (size_t)d * 64 + ln * 4);
    float v = a.x * b.x + a.y * b.y + a.z * b.z + a.w * b.w;
    v += __shfl_down_sync(0xFFFFFFFFu, v, 8, 16);
    v += __shfl_down_sync(0xFFFFFFFFu, v, 4, 16);
    v += __shfl_down_sync(0xFFFFFFFFu, v, 2, 16);
    v += __shfl_down_sync(0xFFFFFFFFu, v, 1, 16);
    if (ln == 0) out[lab] = v;
}

// ---------------------------------------------------------------------------
// Launch
// ---------------------------------------------------------------------------
extern "C" void kernel_launch(void* const* d_in, const int* in_sizes, int n_in,
                              void* d_out, int out_size)
{
    const float* x_mi   = (const float*)d_in[0];
    const float* x_di   = (const float*)d_in[1];
    const float* W_mi   = (const float*)d_in[2];
    const float* b_mi   = (const float*)d_in[3];
    const float* W_di   = (const float*)d_in[4];
    const float* b_di   = (const float*)d_in[5];
    const float* emb_mi = (const float*)d_in[6];
    const float* emb_di = (const float*)d_in[7];

    const float *Wl[3][2], *bl[3][2], *Wr[3][2];  // [layer][0=md,1=dm]
    int idx = 8;
    for (int l = 0; l < 3; l++)
        for (int r = 0; r < 2; r++) {
            Wl[l][r] = (const float*)d_in[idx++];
            bl[l][r] = (const float*)d_in[idx++];
            Wr[l][r] = (const float*)d_in[idx++];
        }
    const int* edge_src  = (const int*)d_in[26];
    const int* edge_dst  = (const int*)d_in[27];
    const int* label_src = (const int*)d_in[28];
    const int* label_dst = (const int*)d_in[29];
    const int E = in_sizes[26];
    const int L = in_sizes[28];
    float* out = (float*)d_out;

    float *hmi[2], *hdi[2], *agg_mi, *agg_di, *deg_mi, *deg_di;
    cudaGetSymbolAddress((void**)&hmi[0], g_hmi_a);
    cudaGetSymbolAddress((void**)&hmi[1], g_hmi_b);
    cudaGetSymbolAddress((void**)&hdi[0], g_hdi_a);
    cudaGetSymbolAddress((void**)&hdi[1], g_hdi_b);
    cudaGetSymbolAddress((void**)&agg_mi, g_agg_mi);
    cudaGetSymbolAddress((void**)&agg_di, g_agg_di);
    cudaGetSymbolAddress((void**)&deg_mi, g_deg_mi);
    cudaGetSymbolAddress((void**)&deg_di, g_deg_di);

    cudaStream_t s = 0;

    cudaMemsetAsync(deg_mi, 0, (size_t)NMI * sizeof(float), s);
    cudaMemsetAsync(deg_di, 0, (size_t)NDI * sizeof(float), s);
    deg_kernel<<<cdiv(E, 256), 256, 0, s>>>(edge_src, edge_dst, E, deg_mi, deg_di);
    inv_kernel<<<cdiv(NMI, 256), 256, 0, s>>>(deg_mi, NMI);
    inv_kernel<<<cdiv(NDI, 256), 256, 0, s>>>(deg_di, NDI);

    // input projections: h = x @ W^T + b + emb
    gemm_bf16x3<<<dim3(cdiv(NDI, BM), 1), 256, 0, s>>>(
        x_di, nullptr, W_di, nullptr, nullptr, b_di, emb_di, hdi[0],
        NDI, 128, 128, 0);
    gemm_bf16x3<<<dim3(cdiv(NMI, BM), 1), 256, 0, s>>>(
        x_mi, nullptr, W_mi, nullptr, nullptr, b_mi, emb_mi, hmi[0],
        NMI, 256, 128, 0);

    const int cin[3]  = {128, 256, 128};
    const int cout[3] = {256, 128, 64};
    int cur = 0;
    for (int l = 0; l < 3; l++) {
        int K  = cin[l];
        int Co = cout[l];
        int relu = (l < 2) ? 1 : 0;

        cudaMemsetAsync(agg_mi, 0, (size_t)NMI * K * sizeof(float), s);
        cudaMemsetAsync(agg_di, 0, (size_t)NDI * K * sizeof(float), s);
        scatter_kernel<<<cdiv(E * 32, 256), 256, 0, s>>>(
            hmi[cur], hdi[cur], edge_src, edge_dst, E, K, agg_di, agg_mi);

        gemm_bf16x3<<<dim3(cdiv(NDI, BM), cdiv(Co, BN)), 256, 0, s>>>(
            agg_di, deg_di, Wl[l][0], hdi[cur], Wr[l][0], bl[l][0], nullptr,
            hdi[cur ^ 1], NDI, K, Co, relu);
        gemm_bf16x3<<<dim3(cdiv(NMI, BM), cdiv(Co, BN)), 256, 0, s>>>(
            agg_mi, deg_mi, Wl[l][1], hmi[cur], Wr[l][1], bl[l][1], nullptr,
            hmi[cur ^ 1], NMI, K, Co, relu);

        cur ^= 1;
    }

    dot_kernel<<<cdiv(L * 16, 256), 256, 0, s>>>(
        hmi[cur], hdi[cur], label_src, label_dst, L, out);
}

// round 7
// speedup vs baseline: 1.3882x; 1.0406x over previous
#include <cuda_runtime.h>
#include <cstdint>

// ---------------------------------------------------------------------------
// Problem constants
// ---------------------------------------------------------------------------
#define NMI 100000
#define NDI 50000
#define HMAX 256

// ---------------------------------------------------------------------------
// Scratch: __device__ globals
// ---------------------------------------------------------------------------
__device__ float g_hmi_a[(size_t)NMI * HMAX];
__device__ float g_hmi_b[(size_t)NMI * HMAX];
__device__ float g_hdi_a[(size_t)NDI * HMAX];
__device__ float g_hdi_b[(size_t)NDI * HMAX];
__device__ float g_agg_mi[(size_t)NMI * HMAX];
__device__ float g_agg_di[(size_t)NDI * HMAX];
__device__ float g_deg_mi[NMI];
__device__ float g_deg_di[NDI];

static inline int cdiv(int a, int b) { return (a + b - 1) / b; }

// ---------------------------------------------------------------------------
// Degree count + inversion
// ---------------------------------------------------------------------------
__global__ void deg_kernel(const int* __restrict__ src, const int* __restrict__ dst,
                           int E, float* __restrict__ deg_mi, float* __restrict__ deg_di)
{
    int i = blockIdx.x * blockDim.x + threadIdx.x;
    if (i < E) {
        atomicAdd(&deg_mi[src[i]], 1.0f);
        atomicAdd(&deg_di[dst[i]], 1.0f);
    }
}

__global__ void inv_kernel(float* __restrict__ deg, int n)
{
    int i = blockIdx.x * blockDim.x + threadIdx.x;
    if (i < n) deg[i] = 1.0f / fmaxf(deg[i], 1.0f);
}

// ---------------------------------------------------------------------------
// Vectorized global reduction
// ---------------------------------------------------------------------------
__device__ __forceinline__ void red_add_v4(float* p, float4 v)
{
    asm volatile("red.global.add.v4.f32 [%0], {%1, %2, %3, %4};"
                 :: "l"(p), "f"(v.x), "f"(v.y), "f"(v.z), "f"(v.w)
                 : "memory");
}

// ---------------------------------------------------------------------------
// One-direction, channel-slab scatter (L2 working-set control):
//   agg[sidx[e]][c0 .. c0+CW) += h[gidx[e]][c0 .. c0+CW)
// One thread per float4; tpe = CW/4 threads per edge (power of two).
// Keeping (h slab + agg slab) <= ~102 MB per pass keeps everything in L2.
// ---------------------------------------------------------------------------
__global__ void scatter_dir(const float* __restrict__ h,
                            const int* __restrict__ gidx,
                            const int* __restrict__ sidx,
                            int E, int Cs, int c0, int tpe_shift,
                            float* __restrict__ agg)
{
    int t = blockIdx.x * blockDim.x + threadIdx.x;
    int e = t >> tpe_shift;
    int j = t & ((1 << tpe_shift) - 1);
    if (e >= E) return;
    const float4* src = (const float4*)(h + (size_t)gidx[e] * Cs + c0);
    float*        dst = agg + (size_t)sidx[e] * Cs + c0;
    red_add_v4(dst + 4 * j, src[j]);
}

// ---------------------------------------------------------------------------
// Split-precision bf16 GEMM (bf16x3: hi/lo split, 3 product terms)
//   D[n,c] = sum_k s(n)*A1[n,k]*W1[c,k] (+ sum_k A2[n,k]*W2[c,k])
//            + bias[c] (+ addend[n,c]) ; optional relu
// CTA: 256 threads (8 warps, 4 along M x 2 along N), tile 128x128,
// warp tile 32x64, BK=16 (one m16n8k16 step per iter).
// ---------------------------------------------------------------------------
#define BM 128
#define BN 128
#define BK 16
#define SR 12          // smem row stride in uints (8 data + 4 pad)

__device__ __forceinline__ unsigned pack_bf16x2(float even, float odd)
{
    unsigned u;
    asm("cvt.rn.bf16x2.f32 %0, %1, %2;" : "=r"(u) : "f"(odd), "f"(even));
    return u;
}

__device__ __forceinline__ void split4(float4 v, unsigned& h0, unsigned& h1,
                                       unsigned& l0, unsigned& l1)
{
    h0 = pack_bf16x2(v.x, v.y);
    h1 = pack_bf16x2(v.z, v.w);
    float ex = v.x - __uint_as_float(h0 << 16);
    float ey = v.y - __uint_as_float(h0 & 0xFFFF0000u);
    float ez = v.z - __uint_as_float(h1 << 16);
    float ew = v.w - __uint_as_float(h1 & 0xFFFF0000u);
    l0 = pack_bf16x2(ex, ey);
    l1 = pack_bf16x2(ez, ew);
}

__device__ __forceinline__ void mma_bf16(float* d, const unsigned* a, unsigned b0, unsigned b1)
{
    asm volatile(
        "mma.sync.aligned.m16n8k16.row.col.f32.bf16.bf16.f32 "
        "{%0,%1,%2,%3}, {%4,%5,%6,%7}, {%8,%9}, {%0,%1,%2,%3};"
        : "+f"(d[0]), "+f"(d[1]), "+f"(d[2]), "+f"(d[3])
        : "r"(a[0]), "r"(a[1]), "r"(a[2]), "r"(a[3]), "r"(b0), "r"(b1));
}

__global__ __launch_bounds__(256, 2)
void gemm_bf16x3(const float* __restrict__ A1, const float* __restrict__ invdeg,
                 const float* __restrict__ W1,
                 const float* __restrict__ A2, const float* __restrict__ W2,
                 const float* __restrict__ bias, const float* __restrict__ addend,
                 float* __restrict__ D, int N, int K, int Co, int relu)
{
    __shared__ unsigned As_h[BM][SR];
    __shared__ unsigned As_l[BM][SR];
    __shared__ unsigned Bs_h[BN][SR];
    __shared__ unsigned Bs_l[BN][SR];

    const int tid  = threadIdx.x;
    const int lane = tid & 31;
    const int wid  = tid >> 5;
    const int wm   = (wid & 3) * 32;   // 4 warps along M
    const int wn   = (wid >> 2) * 64;  // 2 warps along N
    const int gid  = lane >> 2;        // 0..7
    const int tig  = lane & 3;         // 0..3

    const int row0 = blockIdx.x * BM;
    const int col0 = blockIdx.y * BN;

    const int lrow = tid >> 1;         // 0..127
    const int lh   = tid & 1;          // which k8-half this thread loads

    float acc[2][8][4];
#pragma unroll
    for (int i = 0; i < 2; i++)
#pragma unroll
        for (int j = 0; j < 8; j++)
#pragma unroll
            for (int q = 0; q < 4; q++) acc[i][j][q] = 0.0f;

    const int KT = (A2 != nullptr) ? 2 * K : K;

    const int a_row = row0 + lrow;
    const int b_col = col0 + lrow;
    const bool a_ok = a_row < N;
    const bool b_ok = b_col < Co;
    const float sc1 = (invdeg && a_ok) ? invdeg[a_row] : 1.0f;

    float4 pa[2], pb[2];

    auto load_tile = [&](int kt) {
        const bool first = kt < K;                 // BK=16 tile never straddles
        const int  kk0   = first ? kt : (kt - K);
        const float* A   = first ? A1 : A2;
        const float* W   = first ? W1 : W2;
        const float  scl = first ? sc1 : 1.0f;
#pragma unroll
        for (int p = 0; p < 2; p++) {
            const int kk = kk0 + lh * 8 + p * 4;   // contiguous k8 per thread
            float4 v = make_float4(0.f, 0.f, 0.f, 0.f);
            if (a_ok) {
                v = *(const float4*)(A + (size_t)a_row * K + kk);
                v.x *= scl; v.y *= scl; v.z *= scl; v.w *= scl;
            }
            pa[p] = v;
            float4 w = make_float4(0.f, 0.f, 0.f, 0.f);
            if (b_ok) w = *(const float4*)(W + (size_t)b_col * K + kk);
            pb[p] = w;
        }
    };

    auto store_tile = [&]() {
        unsigned h0, h1, h2, h3, l0, l1, l2, l3;
        split4(pa[0], h0, h1, l0, l1);
        split4(pa[1], h2, h3, l2, l3);
        *(uint4*)&As_h[lrow][lh * 4] = make_uint4(h0, h1, h2, h3);
        *(uint4*)&As_l[lrow][lh * 4] = make_uint4(l0, l1, l2, l3);
        split4(pb[0], h0, h1, l0, l1);
        split4(pb[1], h2, h3, l2, l3);
        *(uint4*)&Bs_h[lrow][lh * 4] = make_uint4(h0, h1, h2, h3);
        *(uint4*)&Bs_l[lrow][lh * 4] = make_uint4(l0, l1, l2, l3);
    };

    load_tile(0);

    for (int kt = 0; kt < KT; kt += BK) {
        store_tile();
        __syncthreads();
        if (kt + BK < KT) load_tile(kt + BK);

        unsigned ah[2][4], al[2][4];
#pragma unroll
        for (int mi = 0; mi < 2; mi++) {
            int r = wm + mi * 16 + gid;
            ah[mi][0] = As_h[r][tig];
            ah[mi][1] = As_h[r + 8][tig];
            ah[mi][2] = As_h[r][tig + 4];
            ah[mi][3] = As_h[r + 8][tig + 4];
            al[mi][0] = As_l[r][tig];
            al[mi][1] = As_l[r + 8][tig];
            al[mi][2] = As_l[r][tig + 4];
            al[mi][3] = As_l[r + 8][tig + 4];
        }
#pragma unroll
        for (int ni = 0; ni < 8; ni++) {
            int c = wn + ni * 8 + gid;
            unsigned bh0 = Bs_h[c][tig];
            unsigned bh1 = Bs_h[c][tig + 4];
            unsigned bl0 = Bs_l[c][tig];
            unsigned bl1 = Bs_l[c][tig + 4];
#pragma unroll
            for (int mi = 0; mi < 2; mi++) {
                mma_bf16(acc[mi][ni], al[mi], bh0, bh1);   // lo*hi
                mma_bf16(acc[mi][ni], ah[mi], bl0, bl1);   // hi*lo
                mma_bf16(acc[mi][ni], ah[mi], bh0, bh1);   // hi*hi
            }
        }
        __syncthreads();
    }

    // ---- epilogue ----
#pragma unroll
    for (int mi = 0; mi < 2; mi++) {
#pragma unroll
        for (int ni = 0; ni < 8; ni++) {
            int col = col0 + wn + ni * 8 + 2 * tig;
            if (col >= Co) continue;
            float b0 = bias ? bias[col]     : 0.0f;
            float b1 = bias ? bias[col + 1] : 0.0f;
#pragma unroll
            for (int half = 0; half < 2; half++) {
                int row = row0 + wm + mi * 16 + gid + half * 8;
                if (row >= N) continue;
                float v0 = acc[mi][ni][half * 2 + 0] + b0;
                float v1 = acc[mi][ni][half * 2 + 1] + b1;
                if (addend) {
                    float2 ad = *(const float2*)(addend + (size_t)row * Co + col);
                    v0 += ad.x; v1 += ad.y;
                }
                if (relu) { v0 = fmaxf(v0, 0.0f); v1 = fmaxf(v1, 0.0f); }
                *(float2*)(D + (size_t)row * Co + col) = make_float2(v0, v1);
            }
        }
    }
}

// ---------------------------------------------------------------------------
// Classifier dot product
// ---------------------------------------------------------------------------
__global__ void dot_kernel(const float* __restrict__ hmi, const float* __restrict__ hdi,
                           const int* __restrict__ lsrc, const int* __restrict__ ldst,
                           int L, float* __restrict__ out)
{
    int idx = blockIdx.x * blockDim.x + threadIdx.x;
    int lab = idx >> 4;
    int ln  = idx & 15;
    if (lab >= L) return;
    int s = lsrc[lab];
    int d = ldst[lab];
    float4 a = *(const float4*)(hmi + (size_t)s * 64 + ln * 4);
    float4 b = *(const float4*)(hdi + (size_t)d * 64 + ln * 4);
    float v = a.x * b.x + a.y * b.y + a.z * b.z + a.w * b.w;
    v += __shfl_down_sync(0xFFFFFFFFu, v, 8, 16);
    v += __shfl_down_sync(0xFFFFFFFFu, v, 4, 16);
    v += __shfl_down_sync(0xFFFFFFFFu, v, 2, 16);
    v += __shfl_down_sync(0xFFFFFFFFu, v, 1, 16);
    if (ln == 0) out[lab] = v;
}

// ---------------------------------------------------------------------------
// Launch
// ---------------------------------------------------------------------------
extern "C" void kernel_launch(void* const* d_in, const int* in_sizes, int n_in,
                              void* d_out, int out_size)
{
    const float* x_mi   = (const float*)d_in[0];
    const float* x_di   = (const float*)d_in[1];
    const float* W_mi   = (const float*)d_in[2];
    const float* b_mi   = (const float*)d_in[3];
    const float* W_di   = (const float*)d_in[4];
    const float* b_di   = (const float*)d_in[5];
    const float* emb_mi = (const float*)d_in[6];
    const float* emb_di = (const float*)d_in[7];

    const float *Wl[3][2], *bl[3][2], *Wr[3][2];  // [layer][0=md,1=dm]
    int idx = 8;
    for (int l = 0; l < 3; l++)
        for (int r = 0; r < 2; r++) {
            Wl[l][r] = (const float*)d_in[idx++];
            bl[l][r] = (const float*)d_in[idx++];
            Wr[l][r] = (const float*)d_in[idx++];
        }
    const int* edge_src  = (const int*)d_in[26];
    const int* edge_dst  = (const int*)d_in[27];
    const int* label_src = (const int*)d_in[28];
    const int* label_dst = (const int*)d_in[29];
    const int E = in_sizes[26];
    const int L = in_sizes[28];
    float* out = (float*)d_out;

    float *hmi[2], *hdi[2], *agg_mi, *agg_di, *deg_mi, *deg_di;
    cudaGetSymbolAddress((void**)&hmi[0], g_hmi_a);
    cudaGetSymbolAddress((void**)&hmi[1], g_hmi_b);
    cudaGetSymbolAddress((void**)&hdi[0], g_hdi_a);
    cudaGetSymbolAddress((void**)&hdi[1], g_hdi_b);
    cudaGetSymbolAddress((void**)&agg_mi, g_agg_mi);
    cudaGetSymbolAddress((void**)&agg_di, g_agg_di);
    cudaGetSymbolAddress((void**)&deg_mi, g_deg_mi);
    cudaGetSymbolAddress((void**)&deg_di, g_deg_di);

    cudaStream_t s = 0;

    cudaMemsetAsync(deg_mi, 0, (size_t)NMI * sizeof(float), s);
    cudaMemsetAsync(deg_di, 0, (size_t)NDI * sizeof(float), s);
    deg_kernel<<<cdiv(E, 256), 256, 0, s>>>(edge_src, edge_dst, E, deg_mi, deg_di);
    inv_kernel<<<cdiv(NMI, 256), 256, 0, s>>>(deg_mi, NMI);
    inv_kernel<<<cdiv(NDI, 256), 256, 0, s>>>(deg_di, NDI);

    // input projections: h = x @ W^T + b + emb
    gemm_bf16x3<<<dim3(cdiv(NDI, BM), 1), 256, 0, s>>>(
        x_di, nullptr, W_di, nullptr, nullptr, b_di, emb_di, hdi[0],
        NDI, 128, 128, 0);
    gemm_bf16x3<<<dim3(cdiv(NMI, BM), 1), 256, 0, s>>>(
        x_mi, nullptr, W_mi, nullptr, nullptr, b_mi, emb_mi, hmi[0],
        NMI, 256, 128, 0);

    const int cin[3]  = {128, 256, 128};
    const int cout[3] = {256, 128, 64};
    int cur = 0;
    for (int l = 0; l < 3; l++) {
        int K  = cin[l];
        int Co = cout[l];
        int relu = (l < 2) ? 1 : 0;

        cudaMemsetAsync(agg_mi, 0, (size_t)NMI * K * sizeof(float), s);
        cudaMemsetAsync(agg_di, 0, (size_t)NDI * K * sizeof(float), s);

        // Channel-slabbed, direction-split scatter: each pass's working set
        // (one h slab + one agg slab) stays within L2.
        const int tpe_shift = 5;                 // 32 threads per edge (128 ch)
        const int nthreads  = E * 32;
        for (int c0 = 0; c0 < K; c0 += 128) {
            // md: agg_di[dst] += h_mi[src]
            scatter_dir<<<cdiv(nthreads, 256), 256, 0, s>>>(
                hmi[cur], edge_src, edge_dst, E, K, c0, tpe_shift, agg_di);
        }
        for (int c0 = 0; c0 < K; c0 += 128) {
            // dm: agg_mi[src] += h_di[dst]
            scatter_dir<<<cdiv(nthreads, 256), 256, 0, s>>>(
                hdi[cur], edge_dst, edge_src, E, K, c0, tpe_shift, agg_mi);
        }

        gemm_bf16x3<<<dim3(cdiv(NDI, BM), cdiv(Co, BN)), 256, 0, s>>>(
            agg_di, deg_di, Wl[l][0], hdi[cur], Wr[l][0], bl[l][0], nullptr,
            hdi[cur ^ 1], NDI, K, Co, relu);
        gemm_bf16x3<<<dim3(cdiv(NMI, BM), cdiv(Co, BN)), 256, 0, s>>>(
            agg_mi, deg_mi, Wl[l][1], hmi[cur], Wr[l][1], bl[l][1], nullptr,
            hmi[cur ^ 1], NMI, K, Co, relu);

        cur ^= 1;
    }

    dot_kernel<<<cdiv(L * 16, 256), 256, 0, s>>>(
        hmi[cur], hdi[cur], label_src, label_dst, L, out);
}

// round 8
// speedup vs baseline: 1.5065x; 1.0852x over previous
#include <cuda_runtime.h>
#include <cstdint>

// ---------------------------------------------------------------------------
// Problem constants
// ---------------------------------------------------------------------------
#define NMI 100000
#define NDI 50000
#define HMAX 256

// ---------------------------------------------------------------------------
// Scratch: __device__ globals
// ---------------------------------------------------------------------------
__device__ float g_hmi_a[(size_t)NMI * HMAX];
__device__ float g_hmi_b[(size_t)NMI * HMAX];
__device__ float g_hdi_a[(size_t)NDI * HMAX];
__device__ float g_hdi_b[(size_t)NDI * HMAX];
__device__ float g_agg_mi[(size_t)NMI * HMAX];
__device__ float g_agg_di[(size_t)NDI * HMAX];
__device__ float g_deg_mi[NMI];
__device__ float g_deg_di[NDI];

static inline int cdiv(int a, int b) { return (a + b - 1) / b; }

// ---------------------------------------------------------------------------
// Degree count + inversion
// ---------------------------------------------------------------------------
__global__ void deg_kernel(const int* __restrict__ src, const int* __restrict__ dst,
                           int E, float* __restrict__ deg_mi, float* __restrict__ deg_di)
{
    int i = blockIdx.x * blockDim.x + threadIdx.x;
    if (i < E) {
        atomicAdd(&deg_mi[src[i]], 1.0f);
        atomicAdd(&deg_di[dst[i]], 1.0f);
    }
}

__global__ void inv_kernel(float* __restrict__ deg, int n)
{
    int i = blockIdx.x * blockDim.x + threadIdx.x;
    if (i < n) deg[i] = 1.0f / fmaxf(deg[i], 1.0f);
}

// ---------------------------------------------------------------------------
// Vectorized global reduction
// ---------------------------------------------------------------------------
__device__ __forceinline__ void red_add_v4(float* p, float4 v)
{
    asm volatile("red.global.add.v4.f32 [%0], {%1, %2, %3, %4};"
                 :: "l"(p), "f"(v.x), "f"(v.y), "f"(v.z), "f"(v.w)
                 : "memory");
}

// ---------------------------------------------------------------------------
// One-direction, channel-slab scatter:
//   agg[sidx[e]][c0 .. ) += h[gidx[e]][c0 .. )
// One thread per float4; 2^tpe_shift threads per edge.
// ---------------------------------------------------------------------------
__global__ void scatter_dir(const float* __restrict__ h,
                            const int* __restrict__ gidx,
                            const int* __restrict__ sidx,
                            int E, int Cs, int c0, int tpe_shift,
                            float* __restrict__ agg)
{
    int t = blockIdx.x * blockDim.x + threadIdx.x;
    int e = t >> tpe_shift;
    int j = t & ((1 << tpe_shift) - 1);
    if (e >= E) return;
    const float4* src = (const float4*)(h + (size_t)gidx[e] * Cs + c0);
    float*        dst = agg + (size_t)sidx[e] * Cs + c0;
    red_add_v4(dst + 4 * j, src[j]);
}

// ---------------------------------------------------------------------------
// Split-precision bf16 GEMM (bf16x3: hi/lo split, 3 product terms)
//   D[n,c] = sum_k s(n)*A1[n,k]*W1[c,k] (+ sum_k A2[n,k]*W2[c,k])
//            + bias[c] (+ ascale(n)*addend[n,c]) ; optional relu
// CTA: 256 threads (8 warps, 4 along M x 2 along N), tile 128x128,
// warp tile 32x64, BK=16 (one m16n8k16 step per iter).
// ---------------------------------------------------------------------------
#define BM 128
#define BN 128
#define BK 16
#define SR 12          // smem row stride in uints (8 data + 4 pad)

__device__ __forceinline__ unsigned pack_bf16x2(float even, float odd)
{
    unsigned u;
    asm("cvt.rn.bf16x2.f32 %0, %1, %2;" : "=r"(u) : "f"(odd), "f"(even));
    return u;
}

__device__ __forceinline__ void split4(float4 v, unsigned& h0, unsigned& h1,
                                       unsigned& l0, unsigned& l1)
{
    h0 = pack_bf16x2(v.x, v.y);
    h1 = pack_bf16x2(v.z, v.w);
    float ex = v.x - __uint_as_float(h0 << 16);
    float ey = v.y - __uint_as_float(h0 & 0xFFFF0000u);
    float ez = v.z - __uint_as_float(h1 << 16);
    float ew = v.w - __uint_as_float(h1 & 0xFFFF0000u);
    l0 = pack_bf16x2(ex, ey);
    l1 = pack_bf16x2(ez, ew);
}

__device__ __forceinline__ void mma_bf16(float* d, const unsigned* a, unsigned b0, unsigned b1)
{
    asm volatile(
        "mma.sync.aligned.m16n8k16.row.col.f32.bf16.bf16.f32 "
        "{%0,%1,%2,%3}, {%4,%5,%6,%7}, {%8,%9}, {%0,%1,%2,%3};"
        : "+f"(d[0]), "+f"(d[1]), "+f"(d[2]), "+f"(d[3])
        : "r"(a[0]), "r"(a[1]), "r"(a[2]), "r"(a[3]), "r"(b0), "r"(b1));
}

__global__ __launch_bounds__(256, 2)
void gemm_bf16x3(const float* __restrict__ A1, const float* __restrict__ invdeg,
                 const float* __restrict__ W1,
                 const float* __restrict__ A2, const float* __restrict__ W2,
                 const float* __restrict__ bias, const float* __restrict__ addend,
                 const float* __restrict__ ascale,
                 float* __restrict__ D, int N, int K, int Co, int relu)
{
    __shared__ unsigned As_h[BM][SR];
    __shared__ unsigned As_l[BM][SR];
    __shared__ unsigned Bs_h[BN][SR];
    __shared__ unsigned Bs_l[BN][SR];

    const int tid  = threadIdx.x;
    const int lane = tid & 31;
    const int wid  = tid >> 5;
    const int wm   = (wid & 3) * 32;   // 4 warps along M
    const int wn   = (wid >> 2) * 64;  // 2 warps along N
    const int gid  = lane >> 2;        // 0..7
    const int tig  = lane & 3;         // 0..3

    const int row0 = blockIdx.x * BM;
    const int col0 = blockIdx.y * BN;

    const int lrow = tid >> 1;         // 0..127
    const int lh   = tid & 1;          // which k8-half this thread loads

    float acc[2][8][4];
#pragma unroll
    for (int i = 0; i < 2; i++)
#pragma unroll
        for (int j = 0; j < 8; j++)
#pragma unroll
            for (int q = 0; q < 4; q++) acc[i][j][q] = 0.0f;

    const int KT = (A2 != nullptr) ? 2 * K : K;

    const int a_row = row0 + lrow;
    const int b_col = col0 + lrow;
    const bool a_ok = a_row < N;
    const bool b_ok = b_col < Co;
    const float sc1 = (invdeg && a_ok) ? invdeg[a_row] : 1.0f;

    float4 pa[2], pb[2];

    auto load_tile = [&](int kt) {
        const bool first = kt < K;                 // BK=16 tile never straddles
        const int  kk0   = first ? kt : (kt - K);
        const float* A   = first ? A1 : A2;
        const float* W   = first ? W1 : W2;
        const float  scl = first ? sc1 : 1.0f;
#pragma unroll
        for (int p = 0; p < 2; p++) {
            const int kk = kk0 + lh * 8 + p * 4;   // contiguous k8 per thread
            float4 v = make_float4(0.f, 0.f, 0.f, 0.f);
            if (a_ok) {
                v = *(const float4*)(A + (size_t)a_row * K + kk);
                v.x *= scl; v.y *= scl; v.z *= scl; v.w *= scl;
            }
            pa[p] = v;
            float4 w = make_float4(0.f, 0.f, 0.f, 0.f);
            if (b_ok) w = *(const float4*)(W + (size_t)b_col * K + kk);
            pb[p] = w;
        }
    };

    auto store_tile = [&]() {
        unsigned h0, h1, h2, h3, l0, l1, l2, l3;
        split4(pa[0], h0, h1, l0, l1);
        split4(pa[1], h2, h3, l2, l3);
        *(uint4*)&As_h[lrow][lh * 4] = make_uint4(h0, h1, h2, h3);
        *(uint4*)&As_l[lrow][lh * 4] = make_uint4(l0, l1, l2, l3);
        split4(pb[0], h0, h1, l0, l1);
        split4(pb[1], h2, h3, l2, l3);
        *(uint4*)&Bs_h[lrow][lh * 4] = make_uint4(h0, h1, h2, h3);
        *(uint4*)&Bs_l[lrow][lh * 4] = make_uint4(l0, l1, l2, l3);
    };

    load_tile(0);

    for (int kt = 0; kt < KT; kt += BK) {
        store_tile();
        __syncthreads();
        if (kt + BK < KT) load_tile(kt + BK);

        unsigned ah[2][4], al[2][4];
#pragma unroll
        for (int mi = 0; mi < 2; mi++) {
            int r = wm + mi * 16 + gid;
            ah[mi][0] = As_h[r][tig];
            ah[mi][1] = As_h[r + 8][tig];
            ah[mi][2] = As_h[r][tig + 4];
            ah[mi][3] = As_h[r + 8][tig + 4];
            al[mi][0] = As_l[r][tig];
            al[mi][1] = As_l[r + 8][tig];
            al[mi][2] = As_l[r][tig + 4];
            al[mi][3] = As_l[r + 8][tig + 4];
        }
#pragma unroll
        for (int ni = 0; ni < 8; ni++) {
            int c = wn + ni * 8 + gid;
            unsigned bh0 = Bs_h[c][tig];
            unsigned bh1 = Bs_h[c][tig + 4];
            unsigned bl0 = Bs_l[c][tig];
            unsigned bl1 = Bs_l[c][tig + 4];
#pragma unroll
            for (int mi = 0; mi < 2; mi++) {
                mma_bf16(acc[mi][ni], al[mi], bh0, bh1);   // lo*hi
                mma_bf16(acc[mi][ni], ah[mi], bl0, bl1);   // hi*lo
                mma_bf16(acc[mi][ni], ah[mi], bh0, bh1);   // hi*hi
            }
        }
        __syncthreads();
    }

    // ---- epilogue ----
#pragma unroll
    for (int mi = 0; mi < 2; mi++) {
#pragma unroll
        for (int ni = 0; ni < 8; ni++) {
            int col = col0 + wn + ni * 8 + 2 * tig;
            if (col >= Co) continue;
            float b0 = bias ? bias[col]     : 0.0f;
            float b1 = bias ? bias[col + 1] : 0.0f;
#pragma unroll
            for (int half = 0; half < 2; half++) {
                int row = row0 + wm + mi * 16 + gid + half * 8;
                if (row >= N) continue;
                float v0 = acc[mi][ni][half * 2 + 0] + b0;
                float v1 = acc[mi][ni][half * 2 + 1] + b1;
                if (addend) {
                    float asc = ascale ? ascale[row] : 1.0f;
                    float2 ad = *(const float2*)(addend + (size_t)row * Co + col);
                    v0 = fmaf(asc, ad.x, v0);
                    v1 = fmaf(asc, ad.y, v1);
                }
                if (relu) { v0 = fmaxf(v0, 0.0f); v1 = fmaxf(v1, 0.0f); }
                *(float2*)(D + (size_t)row * Co + col) = make_float2(v0, v1);
            }
        }
    }
}

// ---------------------------------------------------------------------------
// Classifier dot product
// ---------------------------------------------------------------------------
__global__ void dot_kernel(const float* __restrict__ hmi, const float* __restrict__ hdi,
                           const int* __restrict__ lsrc, const int* __restrict__ ldst,
                           int L, float* __restrict__ out)
{
    int idx = blockIdx.x * blockDim.x + threadIdx.x;
    int lab = idx >> 4;
    int ln  = idx & 15;
    if (lab >= L) return;
    int s = lsrc[lab];
    int d = ldst[lab];
    float4 a = *(const float4*)(hmi + (size_t)s * 64 + ln * 4);
    float4 b = *(const float4*)(hdi + (size_t)d * 64 + ln * 4);
    float v = a.x * b.x + a.y * b.y + a.z * b.z + a.w * b.w;
    v += __shfl_down_sync(0xFFFFFFFFu, v, 8, 16);
    v += __shfl_down_sync(0xFFFFFFFFu, v, 4, 16);
    v += __shfl_down_sync(0xFFFFFFFFu, v, 2, 16);
    v += __shfl_down_sync(0xFFFFFFFFu, v, 1, 16);
    if (ln == 0) out[lab] = v;
}

// ---------------------------------------------------------------------------
// Launch
// ---------------------------------------------------------------------------
extern "C" void kernel_launch(void* const* d_in, const int* in_sizes, int n_in,
                              void* d_out, int out_size)
{
    const float* x_mi   = (const float*)d_in[0];
    const float* x_di   = (const float*)d_in[1];
    const float* W_mi   = (const float*)d_in[2];
    const float* b_mi   = (const float*)d_in[3];
    const float* W_di   = (const float*)d_in[4];
    const float* b_di   = (const float*)d_in[5];
    const float* emb_mi = (const float*)d_in[6];
    const float* emb_di = (const float*)d_in[7];

    const float *Wl[3][2], *bl[3][2], *Wr[3][2];  // [layer][0=md,1=dm]
    int idx = 8;
    for (int l = 0; l < 3; l++)
        for (int r = 0; r < 2; r++) {
            Wl[l][r] = (const float*)d_in[idx++];
            bl[l][r] = (const float*)d_in[idx++];
            Wr[l][r] = (const float*)d_in[idx++];
        }
    const int* edge_src  = (const int*)d_in[26];
    const int* edge_dst  = (const int*)d_in[27];
    const int* label_src = (const int*)d_in[28];
    const int* label_dst = (const int*)d_in[29];
    const int E = in_sizes[26];
    const int L = in_sizes[28];
    float* out = (float*)d_out;

    float *hmi[2], *hdi[2], *agg_mi, *agg_di, *deg_mi, *deg_di;
    cudaGetSymbolAddress((void**)&hmi[0], g_hmi_a);
    cudaGetSymbolAddress((void**)&hmi[1], g_hmi_b);
    cudaGetSymbolAddress((void**)&hdi[0], g_hdi_a);
    cudaGetSymbolAddress((void**)&hdi[1], g_hdi_b);
    cudaGetSymbolAddress((void**)&agg_mi, g_agg_mi);
    cudaGetSymbolAddress((void**)&agg_di, g_agg_di);
    cudaGetSymbolAddress((void**)&deg_mi, g_deg_mi);
    cudaGetSymbolAddress((void**)&deg_di, g_deg_di);

    cudaStream_t s = 0;

    cudaMemsetAsync(deg_mi, 0, (size_t)NMI * sizeof(float), s);
    cudaMemsetAsync(deg_di, 0, (size_t)NDI * sizeof(float), s);
    deg_kernel<<<cdiv(E, 256), 256, 0, s>>>(edge_src, edge_dst, E, deg_mi, deg_di);
    inv_kernel<<<cdiv(NMI, 256), 256, 0, s>>>(deg_mi, NMI);
    inv_kernel<<<cdiv(NDI, 256), 256, 0, s>>>(deg_di, NDI);

    // input projections: h = x @ W^T + b + emb
    gemm_bf16x3<<<dim3(cdiv(NDI, BM), 1), 256, 0, s>>>(
        x_di, nullptr, W_di, nullptr, nullptr, b_di, emb_di, nullptr, hdi[0],
        NDI, 128, 128, 0);
    gemm_bf16x3<<<dim3(cdiv(NMI, BM), 1), 256, 0, s>>>(
        x_mi, nullptr, W_mi, nullptr, nullptr, b_mi, emb_mi, nullptr, hmi[0],
        NMI, 256, 128, 0);

    // ------------------------------------------------------------------
    // Layer 1 (K=128 -> Co=256): Co > K, aggregate-then-project (fused 2K)
    // ------------------------------------------------------------------
    {
        const int K = 128, Co = 256;
        cudaMemsetAsync(agg_mi, 0, (size_t)NMI * K * sizeof(float), s);
        cudaMemsetAsync(agg_di, 0, (size_t)NDI * K * sizeof(float), s);
        scatter_dir<<<cdiv(E * 32, 256), 256, 0, s>>>(
            hmi[0], edge_src, edge_dst, E, K, 0, 5, agg_di);
        scatter_dir<<<cdiv(E * 32, 256), 256, 0, s>>>(
            hdi[0], edge_dst, edge_src, E, K, 0, 5, agg_mi);
        gemm_bf16x3<<<dim3(cdiv(NDI, BM), cdiv(Co, BN)), 256, 0, s>>>(
            agg_di, deg_di, Wl[0][0], hdi[0], Wr[0][0], bl[0][0],
            nullptr, nullptr, hdi[1], NDI, K, Co, 1);
        gemm_bf16x3<<<dim3(cdiv(NMI, BM), cdiv(Co, BN)), 256, 0, s>>>(
            agg_mi, deg_mi, Wl[0][1], hmi[0], Wr[0][1], bl[0][1],
            nullptr, nullptr, hmi[1], NMI, K, Co, 1);
    }

    // ------------------------------------------------------------------
    // Layers 2,3 (Co <= K): project-then-aggregate (scatter Co-wide).
    // proj buffers live in the dead double-buffer halves.
    // ------------------------------------------------------------------
    const int cin2[2]  = {256, 128};
    const int cout2[2] = {128, 64};
    int cur = 1;
    for (int li = 0; li < 2; li++) {
        const int K  = cin2[li];
        const int Co = cout2[li];
        const int relu = (li == 0) ? 1 : 0;
        const int tpe_shift = (Co == 128) ? 5 : 4;
        float* proj_mi = hmi[cur ^ 1];
        float* proj_di = hdi[cur ^ 1];

        // project neighbors into output space (no bias, no relu)
        gemm_bf16x3<<<dim3(cdiv(NMI, BM), cdiv(Co, BN)), 256, 0, s>>>(
            hmi[cur], nullptr, Wl[li + 1][0], nullptr, nullptr,
            nullptr, nullptr, nullptr, proj_mi, NMI, K, Co, 0);
        gemm_bf16x3<<<dim3(cdiv(NDI, BM), cdiv(Co, BN)), 256, 0, s>>>(
            hdi[cur], nullptr, Wl[li + 1][1], nullptr, nullptr,
            nullptr, nullptr, nullptr, proj_di, NDI, K, Co, 0);

        cudaMemsetAsync(agg_mi, 0, (size_t)NMI * Co * sizeof(float), s);
        cudaMemsetAsync(agg_di, 0, (size_t)NDI * Co * sizeof(float), s);
        scatter_dir<<<cdiv(E << tpe_shift, 256), 256, 0, s>>>(
            proj_mi, edge_src, edge_dst, E, Co, 0, tpe_shift, agg_di);
        scatter_dir<<<cdiv(E << tpe_shift, 256), 256, 0, s>>>(
            proj_di, edge_dst, edge_src, E, Co, 0, tpe_shift, agg_mi);

        // root GEMM + mean-neighbor addend (row-scaled by invdeg) + bias
        gemm_bf16x3<<<dim3(cdiv(NDI, BM), cdiv(Co, BN)), 256, 0, s>>>(
            hdi[cur], nullptr, Wr[li + 1][0], nullptr, nullptr,
            bl[li + 1][0], agg_di, deg_di, hdi[cur ^ 1], NDI, K, Co, relu);
        gemm_bf16x3<<<dim3(cdiv(NMI, BM), cdiv(Co, BN)), 256, 0, s>>>(
            hmi[cur], nullptr, Wr[li + 1][1], nullptr, nullptr,
            bl[li + 1][1], agg_mi, deg_mi, hmi[cur ^ 1], NMI, K, Co, relu);

        cur ^= 1;
    }

    dot_kernel<<<cdiv(L * 16, 256), 256, 0, s>>>(
        hmi[cur], hdi[cur], label_src, label_dst, L, out);
}

// round 12
// speedup vs baseline: 1.5855x; 1.0524x over previous
#include <cuda_runtime.h>
#include <cstdint>

// ---------------------------------------------------------------------------
// Problem constants
// ---------------------------------------------------------------------------
#define NMI 100000
#define NDI 50000
#define HMAX 256

// ---------------------------------------------------------------------------
// Scratch: __device__ globals
// ---------------------------------------------------------------------------
__device__ float g_hmi_a[(size_t)NMI * HMAX];
__device__ float g_hmi_b[(size_t)NMI * HMAX];
__device__ float g_hdi_a[(size_t)NDI * HMAX];
__device__ float g_hdi_b[(size_t)NDI * HMAX];
__device__ float g_agg_mi[(size_t)NMI * HMAX];
__device__ float g_agg_di[(size_t)NDI * HMAX];
__device__ float g_deg_mi[NMI];
__device__ float g_deg_di[NDI];

static inline int cdiv(int a, int b) { return (a + b - 1) / b; }

// ---------------------------------------------------------------------------
// Degree count + inversion
// ---------------------------------------------------------------------------
__global__ void deg_kernel(const int* __restrict__ src, const int* __restrict__ dst,
                           int E, float* __restrict__ deg_mi, float* __restrict__ deg_di)
{
    int i = blockIdx.x * blockDim.x + threadIdx.x;
    if (i < E) {
        atomicAdd(&deg_mi[src[i]], 1.0f);
        atomicAdd(&deg_di[dst[i]], 1.0f);
    }
}

__global__ void inv_kernel(float* __restrict__ deg, int n)
{
    int i = blockIdx.x * blockDim.x + threadIdx.x;
    if (i < n) deg[i] = 1.0f / fmaxf(deg[i], 1.0f);
}

// ---------------------------------------------------------------------------
// Vectorized global reduction
// ---------------------------------------------------------------------------
__device__ __forceinline__ void red_add_v4(float* p, float4 v)
{
    asm volatile("red.global.add.v4.f32 [%0], {%1, %2, %3, %4};"
                 :: "l"(p), "f"(v.x), "f"(v.y), "f"(v.z), "f"(v.w)
                 : "memory");
}

// ---------------------------------------------------------------------------
// One-direction scatter: agg[sidx[e]] += h[gidx[e]] (Cs floats wide)
// ---------------------------------------------------------------------------
__global__ void scatter_dir(const float* __restrict__ h,
                            const int* __restrict__ gidx,
                            const int* __restrict__ sidx,
                            int E, int Cs, int c0, int tpe_shift,
                            float* __restrict__ agg)
{
    int t = blockIdx.x * blockDim.x + threadIdx.x;
    int e = t >> tpe_shift;
    int j = t & ((1 << tpe_shift) - 1);
    if (e >= E) return;
    const float4* src = (const float4*)(h + (size_t)gidx[e] * Cs + c0);
    float*        dst = agg + (size_t)sidx[e] * Cs + c0;
    red_add_v4(dst + 4 * j, src[j]);
}

// ---------------------------------------------------------------------------
// Split-precision bf16 GEMM (bf16x3), term-major MMA ordering for ILP.
//   D[n,c] = sum_k s(n)*A1[n,k]*W1[c,k] (+ sum_k A2[n,k]*W2[c,k])
//            + bias[c] (+ ascale(n)*addend[n,c]) ; optional relu
// CTA: 256 threads (8 warps, 4 along M x 2 along N), tile 128x128,
// warp tile 32x64, BK=16.
// ---------------------------------------------------------------------------
#define BM 128
#define BN 128
#define BK 16
#define SR 12          // smem row stride in uints (8 data + 4 pad)

__device__ __forceinline__ unsigned pack_bf16x2(float even, float odd)
{
    unsigned u;
    asm("cvt.rn.bf16x2.f32 %0, %1, %2;" : "=r"(u) : "f"(odd), "f"(even));
    return u;
}

__device__ __forceinline__ void split4(float4 v, unsigned& h0, unsigned& h1,
                                       unsigned& l0, unsigned& l1)
{
    h0 = pack_bf16x2(v.x, v.y);
    h1 = pack_bf16x2(v.z, v.w);
    float ex = v.x - __uint_as_float(h0 << 16);
    float ey = v.y - __uint_as_float(h0 & 0xFFFF0000u);
    float ez = v.z - __uint_as_float(h1 << 16);
    float ew = v.w - __uint_as_float(h1 & 0xFFFF0000u);
    l0 = pack_bf16x2(ex, ey);
    l1 = pack_bf16x2(ez, ew);
}

__device__ __forceinline__ void mma_bf16(float* d, const unsigned* a, unsigned b0, unsigned b1)
{
    asm volatile(
        "mma.sync.aligned.m16n8k16.row.col.f32.bf16.bf16.f32 "
        "{%0,%1,%2,%3}, {%4,%5,%6,%7}, {%8,%9}, {%0,%1,%2,%3};"
        : "+f"(d[0]), "+f"(d[1]), "+f"(d[2]), "+f"(d[3])
        : "r"(a[0]), "r"(a[1]), "r"(a[2]), "r"(a[3]), "r"(b0), "r"(b1));
}

__global__ __launch_bounds__(256, 2)
void gemm_bf16x3(const float* __restrict__ A1, const float* __restrict__ invdeg,
                 const float* __restrict__ W1,
                 const float* __restrict__ A2, const float* __restrict__ W2,
                 const float* __restrict__ bias, const float* __restrict__ addend,
                 const float* __restrict__ ascale,
                 float* __restrict__ D, int N, int K, int Co, int relu)
{
    __shared__ unsigned As_h[BM][SR];
    __shared__ unsigned As_l[BM][SR];
    __shared__ unsigned Bs_h[BN][SR];
    __shared__ unsigned Bs_l[BN][SR];

    const int tid  = threadIdx.x;
    const int lane = tid & 31;
    const int wid  = tid >> 5;
    const int wm   = (wid & 3) * 32;   // 4 warps along M
    const int wn   = (wid >> 2) * 64;  // 2 warps along N
    const int gid  = lane >> 2;        // 0..7
    const int tig  = lane & 3;         // 0..3

    const int row0 = blockIdx.x * BM;
    const int col0 = blockIdx.y * BN;

    const int lrow = tid >> 1;         // 0..127
    const int lh   = tid & 1;          // which k8-half this thread loads

    float acc[2][8][4];
#pragma unroll
    for (int i = 0; i < 2; i++)
#pragma unroll
        for (int j = 0; j < 8; j++)
#pragma unroll
            for (int q = 0; q < 4; q++) acc[i][j][q] = 0.0f;

    const int KT = (A2 != nullptr) ? 2 * K : K;

    const int a_row = row0 + lrow;
    const int b_col = col0 + lrow;
    const bool a_ok = a_row < N;
    const bool b_ok = b_col < Co;
    const float sc1 = (invdeg && a_ok) ? invdeg[a_row] : 1.0f;

    float4 pa[2], pb[2];

    auto load_tile = [&](int kt) {
        const bool first = kt < K;                 // BK=16 tile never straddles
        const int  kk0   = first ? kt : (kt - K);
        const float* A   = first ? A1 : A2;
        const float* W   = first ? W1 : W2;
        const float  scl = first ? sc1 : 1.0f;
#pragma unroll
        for (int p = 0; p < 2; p++) {
            const int kk = kk0 + lh * 8 + p * 4;   // contiguous k8 per thread
            float4 v = make_float4(0.f, 0.f, 0.f, 0.f);
            if (a_ok) {
                v = *(const float4*)(A + (size_t)a_row * K + kk);
                v.x *= scl; v.y *= scl; v.z *= scl; v.w *= scl;
            }
            pa[p] = v;
            float4 w = make_float4(0.f, 0.f, 0.f, 0.f);
            if (b_ok) w = *(const float4*)(W + (size_t)b_col * K + kk);
            pb[p] = w;
        }
    };

    auto store_tile = [&]() {
        unsigned h0, h1, h2, h3, l0, l1, l2, l3;
        split4(pa[0], h0, h1, l0, l1);
        split4(pa[1], h2, h3, l2, l3);
        *(uint4*)&As_h[lrow][lh * 4] = make_uint4(h0, h1, h2, h3);
        *(uint4*)&As_l[lrow][lh * 4] = make_uint4(l0, l1, l2, l3);
        split4(pb[0], h0, h1, l0, l1);
        split4(pb[1], h2, h3, l2, l3);
        *(uint4*)&Bs_h[lrow][lh * 4] = make_uint4(h0, h1, h2, h3);
        *(uint4*)&Bs_l[lrow][lh * 4] = make_uint4(l0, l1, l2, l3);
    };

    load_tile(0);

    for (int kt = 0; kt < KT; kt += BK) {
        store_tile();
        __syncthreads();
        if (kt + BK < KT) load_tile(kt + BK);

        // ---- fragment loads ----
        unsigned ah[2][4], al[2][4], bfr[8][2];
#pragma unroll
        for (int mi = 0; mi < 2; mi++) {
            int r = wm + mi * 16 + gid;
            ah[mi][0] = As_h[r][tig];
            ah[mi][1] = As_h[r + 8][tig];
            ah[mi][2] = As_h[r][tig + 4];
            ah[mi][3] = As_h[r + 8][tig + 4];
            al[mi][0] = As_l[r][tig];
            al[mi][1] = As_l[r + 8][tig];
            al[mi][2] = As_l[r][tig + 4];
            al[mi][3] = As_l[r + 8][tig + 4];
        }
#pragma unroll
        for (int ni = 0; ni < 8; ni++) {
            int c = wn + ni * 8 + gid;
            bfr[ni][0] = Bs_h[c][tig];
            bfr[ni][1] = Bs_h[c][tig + 4];
        }

        // ---- term 0: lo(A) * hi(B) — 16 independent MMAs ----
#pragma unroll
        for (int ni = 0; ni < 8; ni++)
#pragma unroll
            for (int mi = 0; mi < 2; mi++)
                mma_bf16(acc[mi][ni], al[mi], bfr[ni][0], bfr[ni][1]);

        // ---- term 1: hi(A) * hi(B) ----
#pragma unroll
        for (int ni = 0; ni < 8; ni++)
#pragma unroll
            for (int mi = 0; mi < 2; mi++)
                mma_bf16(acc[mi][ni], ah[mi], bfr[ni][0], bfr[ni][1]);

        // ---- reload B as lo, term 2: hi(A) * lo(B) ----
#pragma unroll
        for (int ni = 0; ni < 8; ni++) {
            int c = wn + ni * 8 + gid;
            bfr[ni][0] = Bs_l[c][tig];
            bfr[ni][1] = Bs_l[c][tig + 4];
        }
#pragma unroll
        for (int ni = 0; ni < 8; ni++)
#pragma unroll
            for (int mi = 0; mi < 2; mi++)
                mma_bf16(acc[mi][ni], ah[mi], bfr[ni][0], bfr[ni][1]);

        __syncthreads();
    }

    // ---- epilogue ----
#pragma unroll
    for (int mi = 0; mi < 2; mi++) {
#pragma unroll
        for (int ni = 0; ni < 8; ni++) {
            int col = col0 + wn + ni * 8 + 2 * tig;
            if (col >= Co) continue;
            float b0 = bias ? bias[col]     : 0.0f;
            float b1 = bias ? bias[col + 1] : 0.0f;
#pragma unroll
            for (int half = 0; half < 2; half++) {
                int row = row0 + wm + mi * 16 + gid + half * 8;
                if (row >= N) continue;
                float v0 = acc[mi][ni][half * 2 + 0] + b0;
                float v1 = acc[mi][ni][half * 2 + 1] + b1;
                if (addend) {
                    float asc = ascale ? ascale[row] : 1.0f;
                    float2 ad = *(const float2*)(addend + (size_t)row * Co + col);
                    v0 = fmaf(asc, ad.x, v0);
                    v1 = fmaf(asc, ad.y, v1);
                }
                if (relu) { v0 = fmaxf(v0, 0.0f); v1 = fmaxf(v1, 0.0f); }
                *(float2*)(D + (size_t)row * Co + col) = make_float2(v0, v1);
            }
        }
    }
}

// ---------------------------------------------------------------------------
// Classifier dot product
// ---------------------------------------------------------------------------
__global__ void dot_kernel(const float* __restrict__ hmi, const float* __restrict__ hdi,
                           const int* __restrict__ lsrc, const int* __restrict__ ldst,
                           int L, float* __restrict__ out)
{
    int idx = blockIdx.x * blockDim.x + threadIdx.x;
    int lab = idx >> 4;
    int ln  = idx & 15;
    if (lab >= L) return;
    int s = lsrc[lab];
    int d = ldst[lab];
    float4 a = *(const float4*)(hmi + (size_t)s * 64 + ln * 4);
    float4 b = *(const float4*)(hdi + (size_t)d * 64 + ln * 4);
    float v = a.x * b.x + a.y * b.y + a.z * b.z + a.w * b.w;
    v += __shfl_down_sync(0xFFFFFFFFu, v, 8, 16);
    v += __shfl_down_sync(0xFFFFFFFFu, v, 4, 16);
    v += __shfl_down_sync(0xFFFFFFFFu, v, 2, 16);
    v += __shfl_down_sync(0xFFFFFFFFu, v, 1, 16);
    if (ln == 0) out[lab] = v;
}

// ---------------------------------------------------------------------------
// Launch
// ---------------------------------------------------------------------------
extern "C" void kernel_launch(void* const* d_in, const int* in_sizes, int n_in,
                              void* d_out, int out_size)
{
    const float* x_mi   = (const float*)d_in[0];
    const float* x_di   = (const float*)d_in[1];
    const float* W_mi   = (const float*)d_in[2];
    const float* b_mi   = (const float*)d_in[3];
    const float* W_di   = (const float*)d_in[4];
    const float* b_di   = (const float*)d_in[5];
    const float* emb_mi = (const float*)d_in[6];
    const float* emb_di = (const float*)d_in[7];

    const float *Wl[3][2], *bl[3][2], *Wr[3][2];  // [layer][0=md,1=dm]
    int idx = 8;
    for (int l = 0; l < 3; l++)
        for (int r = 0; r < 2; r++) {
            Wl[l][r] = (const float*)d_in[idx++];
            bl[l][r] = (const float*)d_in[idx++];
            Wr[l][r] = (const float*)d_in[idx++];
        }
    const int* edge_src  = (const int*)d_in[26];
    const int* edge_dst  = (const int*)d_in[27];
    const int* label_src = (const int*)d_in[28];
    const int* label_dst = (const int*)d_in[29];
    const int E = in_sizes[26];
    const int L = in_sizes[28];
    float* out = (float*)d_out;

    float *hmi[2], *hdi[2], *agg_mi, *agg_di, *deg_mi, *deg_di;
    cudaGetSymbolAddress((void**)&hmi[0], g_hmi_a);
    cudaGetSymbolAddress((void**)&hmi[1], g_hmi_b);
    cudaGetSymbolAddress((void**)&hdi[0], g_hdi_a);
    cudaGetSymbolAddress((void**)&hdi[1], g_hdi_b);
    cudaGetSymbolAddress((void**)&agg_mi, g_agg_mi);
    cudaGetSymbolAddress((void**)&agg_di, g_agg_di);
    cudaGetSymbolAddress((void**)&deg_mi, g_deg_mi);
    cudaGetSymbolAddress((void**)&deg_di, g_deg_di);

    cudaStream_t s = 0;

    cudaMemsetAsync(deg_mi, 0, (size_t)NMI * sizeof(float), s);
    cudaMemsetAsync(deg_di, 0, (size_t)NDI * sizeof(float), s);
    deg_kernel<<<cdiv(E, 256), 256, 0, s>>>(edge_src, edge_dst, E, deg_mi, deg_di);
    inv_kernel<<<cdiv(NMI, 256), 256, 0, s>>>(deg_mi, NMI);
    inv_kernel<<<cdiv(NDI, 256), 256, 0, s>>>(deg_di, NDI);

    // input projections: h = x @ W^T + b + emb
    gemm_bf16x3<<<dim3(cdiv(NDI, BM), 1), 256, 0, s>>>(
        x_di, nullptr, W_di, nullptr, nullptr, b_di, emb_di, nullptr, hdi[0],
        NDI, 128, 128, 0);
    gemm_bf16x3<<<dim3(cdiv(NMI, BM), 1), 256, 0, s>>>(
        x_mi, nullptr, W_mi, nullptr, nullptr, b_mi, emb_mi, nullptr, hmi[0],
        NMI, 256, 128, 0);

    // ------------------------------------------------------------------
    // Layer 1 (K=128 -> Co=256): Co > K, aggregate-then-project (fused 2K)
    // ------------------------------------------------------------------
    {
        const int K = 128, Co = 256;
        cudaMemsetAsync(agg_mi, 0, (size_t)NMI * K * sizeof(float), s);
        cudaMemsetAsync(agg_di, 0, (size_t)NDI * K * sizeof(float), s);
        scatter_dir<<<cdiv(E * 32, 256), 256, 0, s>>>(
            hmi[0], edge_src, edge_dst, E, K, 0, 5, agg_di);
        scatter_dir<<<cdiv(E * 32, 256), 256, 0, s>>>(
            hdi[0], edge_dst, edge_src, E, K, 0, 5, agg_mi);
        gemm_bf16x3<<<dim3(cdiv(NDI, BM), cdiv(Co, BN)), 256, 0, s>>>(
            agg_di, deg_di, Wl[0][0], hdi[0], Wr[0][0], bl[0][0],
            nullptr, nullptr, hdi[1], NDI, K, Co, 1);
        gemm_bf16x3<<<dim3(cdiv(NMI, BM), cdiv(Co, BN)), 256, 0, s>>>(
            agg_mi, deg_mi, Wl[0][1], hmi[0], Wr[0][1], bl[0][1],
            nullptr, nullptr, hmi[1], NMI, K, Co, 1);
    }

    // ------------------------------------------------------------------
    // Layers 2,3 (Co <= K): project-then-aggregate (scatter Co-wide).
    // ------------------------------------------------------------------
    const int cin2[2]  = {256, 128};
    const int cout2[2] = {128, 64};
    int cur = 1;
    for (int li = 0; li < 2; li++) {
        const int K  = cin2[li];
        const int Co = cout2[li];
        const int relu = (li == 0) ? 1 : 0;
        const int tpe_shift = (Co == 128) ? 5 : 4;
        float* proj_mi = hmi[cur ^ 1];
        float* proj_di = hdi[cur ^ 1];

        // project neighbors into output space (no bias, no relu)
        gemm_bf16x3<<<dim3(cdiv(NMI, BM), cdiv(Co, BN)), 256, 0, s>>>(
            hmi[cur], nullptr, Wl[li + 1][0], nullptr, nullptr,
            nullptr, nullptr, nullptr, proj_mi, NMI, K, Co, 0);
        gemm_bf16x3<<<dim3(cdiv(NDI, BM), cdiv(Co, BN)), 256, 0, s>>>(
            hdi[cur], nullptr, Wl[li + 1][1], nullptr, nullptr,
            nullptr, nullptr, nullptr, proj_di, NDI, K, Co, 0);

        cudaMemsetAsync(agg_mi, 0, (size_t)NMI * Co * sizeof(float), s);
        cudaMemsetAsync(agg_di, 0, (size_t)NDI * Co * sizeof(float), s);
        scatter_dir<<<cdiv(E << tpe_shift, 256), 256, 0, s>>>(
            proj_mi, edge_src, edge_dst, E, Co, 0, tpe_shift, agg_di);
        scatter_dir<<<cdiv(E << tpe_shift, 256), 256, 0, s>>>(
            proj_di, edge_dst, edge_src, E, Co, 0, tpe_shift, agg_mi);

        // root GEMM + mean-neighbor addend (row-scaled by invdeg) + bias
        gemm_bf16x3<<<dim3(cdiv(NDI, BM), cdiv(Co, BN)), 256, 0, s>>>(
            hdi[cur], nullptr, Wr[li + 1][0], nullptr, nullptr,
            bl[li + 1][0], agg_di, deg_di, hdi[cur ^ 1], NDI, K, Co, relu);
        gemm_bf16x3<<<dim3(cdiv(NMI, BM), cdiv(Co, BN)), 256, 0, s>>>(
            hmi[cur], nullptr, Wr[li + 1][1], nullptr, nullptr,
            bl[li + 1][1], agg_mi, deg_mi, hmi[cur ^ 1], NMI, K, Co, relu);

        cur ^= 1;
    }

    dot_kernel<<<cdiv(L * 16, 256), 256, 0, s>>>(
        hmi[cur], hdi[cur], label_src, label_dst, L, out);
}